// round 11
// baseline (speedup 1.0000x reference)
#include <cuda_runtime.h>
#include <cuda_fp16.h>
#include <math.h>

// Problem constants
static constexpr int   N_NODES  = 200000;
static constexpr int   N_USERS  = 100000;
static constexpr int   DIM      = 64;
static constexpr int   LAYERS   = 3;
static constexpr int   E_EDGES  = 3000000;
static constexpr int   N_LINK   = 100000;
static constexpr int   EMB_COLS = (LAYERS + 1) * DIM;             // 256
static constexpr int   CSR_CAP  = E_EDGES + 16 * N_NODES + 64;    // 16-padded capacity

// ---------------------------------------------------------------------------
// Scratch. Feature tables have a ZERO GUARD ROW at index 0 (node v -> row v+1).
// Guard rows are never written (zero from .bss forever). CSR entries store
// (src+1); padding entries are 0 and gather the guard row (adds 0.0, L1-hot).
// deg/csr/totals are re-zeroed by k_tail at the END of each call.
//
// fp16 GATHER TABLES: the convs' random gathers read dense __half rows
// (128B) from g_hxs / g_hxt; accumulation + GEMM + pred remain fp32.
// ---------------------------------------------------------------------------
__device__ int    g_deg_s[N_NODES],  g_deg_t[N_NODES];
__device__ int2   g_seg_s[N_NODES],  g_seg_t[N_NODES];   // {start, deg}
__device__ int    g_cur_s[N_NODES],  g_cur_t[N_NODES];
__device__ int    g_tot_s,           g_tot_t;
__device__ int    g_csr_s[CSR_CAP],  g_csr_t[CSR_CAP];
__device__ float  g_invdeg_s[N_NODES], g_invdeg_t[N_NODES];
__device__ float  g_means[(size_t)(N_NODES + 1) * DIM];       // +guard (fp32)
__device__ float  g_meant[(size_t)(N_NODES + 1) * DIM];       // +guard (fp32)
__device__ __half g_hxs [(size_t)(N_NODES + 1) * DIM];        // fp16 gather (source)
__device__ __half g_hxt [(size_t)(N_NODES + 1) * DIM];        // fp16 gather (target)
__device__ float  g_embs [(size_t)(N_NODES + 1) * EMB_COLS];  // fp32 [emb|x1|x2|x3]

// ---------------------------------------------------------------------------
// (1) Histogram degrees for both graphs (deg arrays are pre-zeroed).
// ---------------------------------------------------------------------------
__global__ void k_hist(const int* __restrict__ s_dst, const int* __restrict__ t_dst) {
    int e = blockIdx.x * blockDim.x + threadIdx.x;
    if (e < E_EDGES) {
        atomicAdd(&g_deg_s[s_dst[e]], 1);
        atomicAdd(&g_deg_t[t_dst[e]], 1);
    }
}

// ---------------------------------------------------------------------------
// (2) Claim 16-padded CSR segments (block-aggregated scan, 1 atomic per
// block per graph). Also: invdeg; copy emb into g_embs block 0 (fp32) and
// into g_hxs (fp16 layer-0 gather table, shared by both graphs).
// ---------------------------------------------------------------------------
__global__ void k_offsets(const float4* __restrict__ emb4) {
    __shared__ int sh_s[256], sh_t[256];
    __shared__ int base_s, base_t;
    int t = threadIdx.x;
    int i = blockIdx.x * 256 + t;

    int ds = 0, dt = 0;
    if (i < N_NODES) { ds = g_deg_s[i]; dt = g_deg_t[i]; }
    int ps = (ds + 15) & ~15, pt = (dt + 15) & ~15;
    sh_s[t] = ps; sh_t[t] = pt;
    __syncthreads();
    #pragma unroll
    for (int off = 1; off < 256; off <<= 1) {
        int a = (t >= off) ? sh_s[t - off] : 0;
        int b = (t >= off) ? sh_t[t - off] : 0;
        __syncthreads();
        sh_s[t] += a; sh_t[t] += b;
        __syncthreads();
    }
    if (t == 255) {
        base_s = atomicAdd(&g_tot_s, sh_s[255]);
        base_t = atomicAdd(&g_tot_t, sh_t[255]);
    }
    __syncthreads();
    if (i < N_NODES) {
        int rs = base_s + sh_s[t] - ps;
        int rt = base_t + sh_t[t] - pt;
        g_seg_s[i] = make_int2(rs, ds);  g_cur_s[i] = rs;
        g_seg_t[i] = make_int2(rt, dt);  g_cur_t[i] = rt;
        g_invdeg_s[i] = 1.f / fmaxf((float)ds, 1.f);
        g_invdeg_t[i] = 1.f / fmaxf((float)dt, 1.f);
    }
    // emb -> g_embs (fp32, rows 1..N) and g_hxs (fp16)
    const long NF4 = (long)N_NODES * (DIM / 4);
    long stride = (long)gridDim.x * blockDim.x;
    for (long j = (long)blockIdx.x * 256 + t; j < NF4; j += stride) {
        long v = j >> 4;
        int  d = (int)(j & 15);
        float4 f = emb4[j];
        reinterpret_cast<float4*>(g_embs)[(v + 1) * (EMB_COLS / 4) + d] = f;
        __half2* h2 = reinterpret_cast<__half2*>(g_hxs) + (v + 1) * (DIM / 2) + 2 * d;
        h2[0] = __floats2half2_rn(f.x, f.y);
        h2[1] = __floats2half2_rn(f.z, f.w);
    }
}

// ---------------------------------------------------------------------------
// (3) Fill CSR: store src+1 (0 is reserved for the zero guard row).
// ---------------------------------------------------------------------------
__global__ void k_fill(const int* __restrict__ s_src, const int* __restrict__ s_dst,
                       const int* __restrict__ t_src, const int* __restrict__ t_dst) {
    int e = blockIdx.x * blockDim.x + threadIdx.x;
    if (e < E_EDGES) {
        int ps = atomicAdd(&g_cur_s[s_dst[e]], 1);
        g_csr_s[ps] = s_src[e] + 1;
        int pt = atomicAdd(&g_cur_t[t_dst[e]], 1);
        g_csr_t[pt] = t_src[e] + 1;
    }
}

// ---------------------------------------------------------------------------
// (4..) fp16 gather conv: HALF-WARP per node. Row = 64 halves = 128B;
// a lane loads uint4 (8 halves), so 8 lanes cover a row and each half-warp
// round gathers 2 neighbors. Per 16-group: 1 csr LDG + 8 branch-free rounds
// of 2 independent LDG.128. fp32 accumulation; writes fp32 pre-scaled mean.
// ---------------------------------------------------------------------------
__global__ void __launch_bounds__(256)
k_conv(const __half* __restrict__ x,
       const int2* __restrict__ seg, const float* __restrict__ invd,
       const int* __restrict__ csr, float* __restrict__ om, int nN) {
    int w = (blockIdx.x * blockDim.x + threadIdx.x) >> 5;
    if (w >= nN / 2) return;
    int      lane = threadIdx.x & 31;
    int      h    = lane >> 4;                      // half-warp id
    int      q    = lane & 15;                      // id within half-warp
    unsigned hm   = h ? 0xFFFF0000u : 0x0000FFFFu;
    int      v    = 2 * w + h;                      // 0-based node

    int2 sd    = __ldg(&seg[v]);                    // {start, deg}
    int  start = sd.x;
    int  p16   = (sd.y + 15) & ~15;

    int nb = q >> 3;                                // which of 2 neighbors/round
    int ck = q & 7;                                 // 16B chunk within row

    float acc[8] = {0.f, 0.f, 0.f, 0.f, 0.f, 0.f, 0.f, 0.f};

    for (int j0 = 0; j0 < p16; j0 += 16) {
        int idx = __ldg(&csr[start + j0 + q]);      // 16 entries per half-warp
        #pragma unroll
        for (int r = 0; r < 8; r++) {
            int s = __shfl_sync(hm, idx, h * 16 + 2 * r + nb);
            uint4 u = __ldg(reinterpret_cast<const uint4*>(
                                x + (size_t)s * DIM) + ck);
            float2 f;
            f = __half22float2(*reinterpret_cast<const __half2*>(&u.x));
            acc[0] += f.x; acc[1] += f.y;
            f = __half22float2(*reinterpret_cast<const __half2*>(&u.y));
            acc[2] += f.x; acc[3] += f.y;
            f = __half22float2(*reinterpret_cast<const __half2*>(&u.z));
            acc[4] += f.x; acc[5] += f.y;
            f = __half22float2(*reinterpret_cast<const __half2*>(&u.w));
            acc[6] += f.x; acc[7] += f.y;
        }
    }

    // fold the two neighbor classes (q and q+8); valid in lanes with nb==0
    #pragma unroll
    for (int i = 0; i < 8; i++)
        acc[i] += __shfl_down_sync(hm, acc[i], 8);

    if (nb == 0) {                                  // lanes q=0..7 of each half
        float iv = invd[v];
        float4 o0 = make_float4(acc[0] * iv, acc[1] * iv, acc[2] * iv, acc[3] * iv);
        float4 o1 = make_float4(acc[4] * iv, acc[5] * iv, acc[6] * iv, acc[7] * iv);
        float4* row = reinterpret_cast<float4*>(om + (size_t)(v + 1) * DIM);
        row[2 * ck]     = o0;                       // cols 8ck .. 8ck+7
        row[2 * ck + 1] = o1;
    }
}

// ---------------------------------------------------------------------------
// Combine: users get mix GEMM ue=[ms|mt]@W^T+b (fp32, float4-packed smem W).
// Writes fp32 source slice into g_embs(layer+1); fp16 copies into the next
// layer's gather tables g_hxs / g_hxt (skipped on the last layer).
// ---------------------------------------------------------------------------
__global__ void __launch_bounds__(256)
k_combine(const float* __restrict__ mix_w, const float* __restrict__ mix_b,
          int layer, int write_next) {
    // WT4[k2*32 + ln] = { W[ln][2k2], W[ln+32][2k2], W[ln][2k2+1], W[ln+32][2k2+1] }
    __shared__ float4 WT4[64 * 32];    // 32 KB
    __shared__ float  BB[64];

    const float* W = mix_w + (size_t)layer * 64 * 128;
    for (int i = threadIdx.x; i < 64 * 32; i += blockDim.x) {
        int k2 = i >> 5, ln = i & 31;
        WT4[i] = make_float4(W[ln * 128 + 2 * k2],     W[(ln + 32) * 128 + 2 * k2],
                             W[ln * 128 + 2 * k2 + 1], W[(ln + 32) * 128 + 2 * k2 + 1]);
    }
    if (threadIdx.x < 64) BB[threadIdx.x] = mix_b[layer * 64 + threadIdx.x];
    __syncthreads();

    int lane = threadIdx.x & 31;
    int warp = threadIdx.x >> 5;
    int wpb  = blockDim.x >> 5;

    for (int v = blockIdx.x * wpb + warp; v < N_NODES; v += gridDim.x * wpb) {
        size_t base = (size_t)(v + 1) * DIM;

        float ms0 = g_means[base + lane];
        float ms1 = g_means[base + 32 + lane];
        float mt0 = g_meant[base + lane];
        float mt1 = g_meant[base + 32 + lane];

        float o0, o1, t0, t1;
        if (v < N_USERS) {
            float a0 = BB[lane], a1 = BB[lane + 32];
            #pragma unroll
            for (int k2 = 0; k2 < 16; k2++) {
                float m0 = __shfl_sync(0xffffffffu, ms0, 2 * k2);
                float m1 = __shfl_sync(0xffffffffu, ms0, 2 * k2 + 1);
                float4 qv = WT4[k2 * 32 + lane];
                a0 += m0 * qv.x + m1 * qv.z;
                a1 += m0 * qv.y + m1 * qv.w;
            }
            #pragma unroll
            for (int k2 = 0; k2 < 16; k2++) {
                float m0 = __shfl_sync(0xffffffffu, ms1, 2 * k2);
                float m1 = __shfl_sync(0xffffffffu, ms1, 2 * k2 + 1);
                float4 qv = WT4[(16 + k2) * 32 + lane];
                a0 += m0 * qv.x + m1 * qv.z;
                a1 += m0 * qv.y + m1 * qv.w;
            }
            #pragma unroll
            for (int k2 = 0; k2 < 16; k2++) {
                float m0 = __shfl_sync(0xffffffffu, mt0, 2 * k2);
                float m1 = __shfl_sync(0xffffffffu, mt0, 2 * k2 + 1);
                float4 qv = WT4[(32 + k2) * 32 + lane];
                a0 += m0 * qv.x + m1 * qv.z;
                a1 += m0 * qv.y + m1 * qv.w;
            }
            #pragma unroll
            for (int k2 = 0; k2 < 16; k2++) {
                float m0 = __shfl_sync(0xffffffffu, mt1, 2 * k2);
                float m1 = __shfl_sync(0xffffffffu, mt1, 2 * k2 + 1);
                float4 qv = WT4[(48 + k2) * 32 + lane];
                a0 += m0 * qv.x + m1 * qv.z;
                a1 += m0 * qv.y + m1 * qv.w;
            }
            o0 = a0; o1 = a1; t0 = a0; t1 = a1;
        } else {
            o0 = ms0; o1 = ms1; t0 = mt0; t1 = mt1;
        }

        if (write_next) {
            __half* hs = g_hxs + base;
            hs[lane]      = __float2half_rn(o0);
            hs[lane + 32] = __float2half_rn(o1);
            __half* ht = g_hxt + base;
            ht[lane]      = __float2half_rn(t0);
            ht[lane + 32] = __float2half_rn(t1);
        }
        float* er = g_embs + (size_t)(v + 1) * EMB_COLS + (size_t)(layer + 1) * DIM;
        er[lane]      = o0;
        er[lane + 32] = o1;
    }
}

// ---------------------------------------------------------------------------
// Prediction head: warp per link, float4 loads (1-based rows, fp32).
// ---------------------------------------------------------------------------
__global__ void k_pred(const int* __restrict__ link,
                       const float* __restrict__ pred_w,
                       const float* __restrict__ pred_b,
                       float* __restrict__ out) {
    __shared__ float4 pw4[128];                       // 512 floats
    for (int i = threadIdx.x; i < 128; i += blockDim.x)
        pw4[i] = reinterpret_cast<const float4*>(pred_w)[i];
    __syncthreads();

    int lane = threadIdx.x & 31;
    int warp = threadIdx.x >> 5;
    int j = blockIdx.x * (blockDim.x >> 5) + warp;
    if (j >= N_LINK) return;

    int u  = __ldg(&link[j]) + 1;
    int it = __ldg(&link[N_LINK + j]) + 1;
    const float4* ue4 = reinterpret_cast<const float4*>(g_embs + (size_t)u  * EMB_COLS);
    const float4* ie4 = reinterpret_cast<const float4*>(g_embs + (size_t)it * EMB_COLS);

    float acc = 0.f;
    #pragma unroll
    for (int r = 0; r < 2; r++) {
        int idx = lane + r * 32;                      // 0..63
        float4 a = __ldg(&ue4[idx]);
        float4 w = pw4[idx];
        acc += a.x * w.x + a.y * w.y + a.z * w.z + a.w * w.w;
        float4 b = __ldg(&ie4[idx]);
        float4 w2 = pw4[64 + idx];
        acc += b.x * w2.x + b.y * w2.y + b.z * w2.z + b.w * w2.w;
    }

    #pragma unroll
    for (int o = 16; o > 0; o >>= 1) acc += __shfl_down_sync(0xffffffffu, acc, o);

    if (lane == 0) {
        float z = acc + pred_b[0];
        z = (z >= 0.f) ? z : 0.01f * z;
        out[j] = 1.f / (1.f + expf(-z));
    }
}

// ---------------------------------------------------------------------------
// Tail: restore the zero state (deg, totals, csr) for the next call.
// ---------------------------------------------------------------------------
__global__ void k_tail() {
    int stride = gridDim.x * blockDim.x;
    int t0 = blockIdx.x * blockDim.x + threadIdx.x;
    for (int i = t0; i < CSR_CAP; i += stride) { g_csr_s[i] = 0; g_csr_t[i] = 0; }
    for (int i = t0; i < N_NODES; i += stride) { g_deg_s[i] = 0; g_deg_t[i] = 0; }
    if (t0 == 0) { g_tot_s = 0; g_tot_t = 0; }
}

// ---------------------------------------------------------------------------
// Launch.
// ---------------------------------------------------------------------------
extern "C" void kernel_launch(void* const* d_in, const int* in_sizes, int n_in,
                              void* d_out, int out_size) {
    const int*   sei    = (const int*)  d_in[0];
    const int*   tei    = (const int*)  d_in[1];
    const int*   link   = (const int*)  d_in[2];
    const float* emb    = (const float*)d_in[3];
    const float* mix_w  = (const float*)d_in[4];
    const float* mix_b  = (const float*)d_in[5];
    const float* pred_w = (const float*)d_in[6];
    const float* pred_b = (const float*)d_in[7];
    float*       out    = (float*)d_out;

    const int* s_src = sei;
    const int* s_dst = sei + E_EDGES;
    const int* t_src = tei;
    const int* t_dst = tei + E_EDGES;

    k_hist   <<<(E_EDGES + 255) / 256, 256>>>(s_dst, t_dst);
    k_offsets<<<(N_NODES + 255) / 256, 256>>>(reinterpret_cast<const float4*>(emb));
    k_fill   <<<(E_EDGES + 255) / 256, 256>>>(s_src, s_dst, t_src, t_dst);

    for (int l = 0; l < LAYERS; l++) {
        // source conv gathers g_hxs (layer 0: fp16 emb; else fp16 combine out)
        k_conv<<<(N_NODES / 2 * 32 + 255) / 256, 256>>>(
            g_hxs, g_seg_s, g_invdeg_s, g_csr_s, g_means, N_NODES);
        // target conv: layer 0 gathers g_hxs (same emb table); else g_hxt.
        // Last layer: only user rows are ever consumed.
        const __half* xt = (l == 0) ? g_hxs : g_hxt;
        int           nT = (l == LAYERS - 1) ? N_USERS : N_NODES;
        k_conv<<<(nT / 2 * 32 + 255) / 256, 256>>>(
            xt, g_seg_t, g_invdeg_t, g_csr_t, g_meant, nT);

        k_combine<<<2960, 256>>>(mix_w, mix_b, l, l < LAYERS - 1 ? 1 : 0);
    }

    k_pred<<<(N_LINK + 7) / 8, 256>>>(link, pred_w, pred_b, out);
    k_tail<<<4096, 256>>>();
}